// round 3
// baseline (speedup 1.0000x reference)
#include <cuda_runtime.h>
#include <math.h>

#define NPTS 131072

// ------------- global scratch (static device arrays: allowed) -------------
__device__ float g_origin[2];
__device__ float g_y[NPTS * 2];
__device__ float g_jinv[NPTS * 4];
__device__ float g_xdh[NPTS * 2];

__device__ __forceinline__ float eluf(float v) { return v > 0.f ? v : expm1f(v); }
__device__ __forceinline__ float softplusf(float p) {
    return fmaxf(p, 0.f) + log1pf(expf(-fabsf(p)));
}

// ========================= K0: origin = taskmap(0) =========================
__global__ void k_origin(const float* __restrict__ w1, const float* __restrict__ b1,
                         const float* __restrict__ w2, const float* __restrict__ b2,
                         const float* __restrict__ w3, const float* __restrict__ b3,
                         const float* __restrict__ w4, const float* __restrict__ b4,
                         const float* __restrict__ w5, const float* __restrict__ b5,
                         const float* __restrict__ w6, const float* __restrict__ b6) {
    __shared__ float h[100], h2[100], y1s[2];
    int j = threadIdx.x;
    if (j < 100) h[j] = tanhf(b1[j]);
    __syncthreads();
    if (j < 100) {
        float a = b2[j];
        for (int k = 0; k < 100; k++) a = fmaf(h[k], w2[k * 100 + j], a);
        h2[j] = tanhf(a);
    }
    __syncthreads();
    if (j < 2) {
        float a = b3[j];
        for (int k = 0; k < 100; k++) a = fmaf(h2[k], w3[k * 2 + j], a);
        y1s[j] = a;  // + z(=0)
    }
    __syncthreads();
    if (j < 100) {
        float a = fmaf(y1s[0], w4[j], fmaf(y1s[1], w4[100 + j], b4[j]));
        h[j] = eluf(a);
    }
    __syncthreads();
    if (j < 100) {
        float a = b5[j];
        for (int k = 0; k < 100; k++) a = fmaf(h[k], w5[k * 100 + j], a);
        h2[j] = eluf(a);
    }
    __syncthreads();
    if (j < 2) {
        float a = b6[j];
        for (int k = 0; k < 100; k++) a = fmaf(h2[k], w6[k * 2 + j], a);
        float s = softplusf(a);
        g_origin[j] = (1.f + s) * y1s[j];
    }
}

// ========================= K1: taskmap + Jacobian ==========================
// Block: 64 points, 192 rows (value, tangent0, tangent1), 384 threads (2/row).
// ACT: 0 = tanh, 1 = elu
template <int ACT>
__device__ __forceinline__ void tm_mid(const float* __restrict__ W, const float* __restrict__ b,
                                       float* ws, const float* inb, float* outb,
                                       int tid, int r, int comp, int p, int jbase, int jcnt) {
    // stage W (100x100) into smem, zero-pad tail so overshooting float4 reads are safe
    for (int i = tid; i < 10016; i += 384) ws[i] = (i < 10000) ? W[i] : 0.f;
    __syncthreads();
    float acc[52];
#pragma unroll
    for (int t = 0; t < 52; t++) acc[t] = 0.f;
    const float* inrow = inb + r * 101;
    for (int k = 0; k < 100; k++) {
        float a = inrow[k];
        const float4* wr = reinterpret_cast<const float4*>(ws + k * 100 + jbase);
#pragma unroll
        for (int t = 0; t < 13; t++) {
            float4 w = wr[t];
            acc[4 * t + 0] = fmaf(a, w.x, acc[4 * t + 0]);
            acc[4 * t + 1] = fmaf(a, w.y, acc[4 * t + 1]);
            acc[4 * t + 2] = fmaf(a, w.z, acc[4 * t + 2]);
            acc[4 * t + 3] = fmaf(a, w.w, acc[4 * t + 3]);
        }
    }
    float* outrow = outb + r * 101;
    if (comp == 0) {
        for (int jj = 0; jj < jcnt; jj++) {
            float v = acc[jj] + b[jbase + jj];
            outrow[jbase + jj] = (ACT == 0) ? tanhf(v) : eluf(v);
        }
    } else {
        for (int jj = 0; jj < jcnt; jj++) outrow[jbase + jj] = acc[jj];
    }
    __syncthreads();
    if (comp != 0) {
        const float* vrow = outb + p * 101;
        for (int jj = 0; jj < jcnt; jj++) {
            float h = vrow[jbase + jj];
            float d = (ACT == 0) ? (1.f - h * h) : (h > 0.f ? 1.f : h + 1.f);
            outrow[jbase + jj] *= d;
        }
    }
    __syncthreads();
}

__global__ __launch_bounds__(384, 1) void k_taskmap(
    const float* __restrict__ x,
    const float* __restrict__ w1, const float* __restrict__ b1,
    const float* __restrict__ w2, const float* __restrict__ b2,
    const float* __restrict__ w3, const float* __restrict__ b3,
    const float* __restrict__ w4, const float* __restrict__ b4,
    const float* __restrict__ w5, const float* __restrict__ b5,
    const float* __restrict__ w6, const float* __restrict__ b6) {
    extern __shared__ float sm[];
    float* ws   = sm;                  // 10016
    float* bufA = sm + 10016;          // 192*101
    float* bufB = bufA + 192 * 101;    // 192*101
    float* xs   = bufB + 192 * 101;    // 128
    float* v2   = xs + 128;            // 384  (y1 / dy1 per row)
    float* ss   = v2 + 384;            // 128  (softplus s per point)
    float* sg   = ss + 128;            // 128  (sigmoid per point)
    float* Jsh  = sg + 128;            // 256  (J per point)

    const int tid = threadIdx.x;
    const int r = tid >> 1;            // row 0..191
    const int half = tid & 1;
    const int comp = r / 64;           // 0 value, 1 tangent-x0, 2 tangent-x1
    const int p = r % 64;              // local point
    const int jbase = half * 52;
    const int jcnt = half ? 48 : 52;
    const int gp = blockIdx.x * 64 + p;

    if (tid < 128) xs[tid] = x[blockIdx.x * 128 + tid];
    __syncthreads();

    // ---- tm1 layer1 (2 -> 100, tanh) ----
    {
        float x0 = xs[p * 2 + 0], x1 = xs[p * 2 + 1];
        float* row = bufA + r * 101;
        if (comp == 0) {
            for (int jj = 0; jj < jcnt; jj++) {
                int j = jbase + jj;
                row[j] = tanhf(fmaf(x0, w1[j], fmaf(x1, w1[100 + j], b1[j])));
            }
        } else {
            const float* wr = w1 + (comp - 1) * 100;  // e_c @ W1 = row c of W1
            for (int jj = 0; jj < jcnt; jj++) row[jbase + jj] = wr[jbase + jj];
        }
        __syncthreads();
        if (comp) {
            const float* vrow = bufA + p * 101;
            for (int jj = 0; jj < jcnt; jj++) {
                int j = jbase + jj;
                float h = vrow[j];
                row[j] *= (1.f - h * h);
            }
        }
        __syncthreads();
    }

    // ---- tm1 layer2 (100 -> 100, tanh) ----
    tm_mid<0>(w2, b2, ws, bufA, bufB, tid, r, comp, p, jbase, jcnt);

    // ---- tm1 layer3 (100 -> 2) + residual / e_c ----
    {
        const float* inrow = bufB + r * 101;
        float acc = 0.f;
        for (int k = 0; k < 100; k++) acc = fmaf(inrow[k], w3[k * 2 + half], acc);
        float val;
        if (comp == 0) val = acc + b3[half] + xs[p * 2 + half];
        else val = acc + (((comp - 1) == half) ? 1.f : 0.f);
        v2[r * 2 + half] = val;
    }
    __syncthreads();

    // ---- tm2 layer1 (2 -> 100, elu) ----
    {
        float i0 = v2[r * 2 + 0], i1 = v2[r * 2 + 1];
        float* row = bufA + r * 101;
        for (int jj = 0; jj < jcnt; jj++) {
            int j = jbase + jj;
            float raw = fmaf(i0, w4[j], i1 * w4[100 + j]);
            if (comp == 0) raw = eluf(raw + b4[j]);
            row[j] = raw;
        }
        __syncthreads();
        if (comp) {
            const float* vrow = bufA + p * 101;
            for (int jj = 0; jj < jcnt; jj++) {
                int j = jbase + jj;
                float h = vrow[j];
                row[j] *= (h > 0.f ? 1.f : h + 1.f);
            }
        }
        __syncthreads();
    }

    // ---- tm2 layer2 (100 -> 100, elu) ----
    tm_mid<1>(w5, b5, ws, bufA, bufB, tid, r, comp, p, jbase, jcnt);

    // ---- tm2 layer3 (100 -> 2) + softplus gate, y output, J, pinv(J) ----
    {
        const float* inrow = bufB + r * 101;
        float acc = 0.f;
        for (int k = 0; k < 100; k++) acc = fmaf(inrow[k], w6[k * 2 + half], acc);
        if (comp == 0) {
            float pv = acc + b6[half];
            float s = softplusf(pv);
            ss[p * 2 + half] = s;
            sg[p * 2 + half] = 1.f / (1.f + expf(-pv));
            float y1 = v2[r * 2 + half];
            g_y[gp * 2 + half] = (1.f + s) * y1 - g_origin[half];
        }
        __syncthreads();
        if (comp) {
            int c = comp - 1, i = half;
            float s = ss[p * 2 + i];
            float ds = sg[p * 2 + i] * acc;  // acc = dp_i^{(c)}
            Jsh[p * 4 + i * 2 + c] = fmaf(ds, v2[p * 2 + i], (1.f + s) * v2[r * 2 + i]);
        }
        __syncthreads();
        if (comp == 0 && half == 0) {
            float a = Jsh[p * 4 + 0], b_ = Jsh[p * 4 + 1];
            float c = Jsh[p * 4 + 2], d = Jsh[p * 4 + 3];
            float det = a * d - b_ * c;
            float n2 = a * a + b_ * b_ + c * c + d * d;
            float ia, ib, ic, id;
            if (fabsf(det) > 1e-10f * n2) {
                float inv = 1.f / det;
                ia = d * inv; ib = -b_ * inv; ic = -c * inv; id = a * inv;
            } else {  // (near) rank-1 pseudo-inverse: A^T / ||A||_F^2
                float inv = (n2 > 0.f) ? 1.f / n2 : 0.f;
                ia = a * inv; ib = c * inv; ic = b_ * inv; id = d * inv;
            }
            float4 o; o.x = ia; o.y = ib; o.z = ic; o.w = id;
            *reinterpret_cast<float4*>(g_jinv + gp * 4) = o;
        }
    }
}

// ====================== K2: vv net + yd + J^-1 * yd_n ======================
__global__ __launch_bounds__(256, 1) void k_vv(
    const float* __restrict__ w1, const float* __restrict__ b1, const float* __restrict__ a1p,
    const float* __restrict__ w2, const float* __restrict__ b2, const float* __restrict__ a2p,
    const float* __restrict__ w3, const float* __restrict__ b3) {
    extern __shared__ float sm[];
    float* wchunk = sm;                // 15008 (50x300 + pad)
    float* bufA = sm + 15008;          // 64*301
    float* bufB = bufA + 64 * 301;     // 64*301
    float* ys = bufB + 64 * 301;       // 128

    const int tid = threadIdx.x;
    const int p = tid >> 2;
    const int q = tid & 3;
    const int jbase = q * 76;
    const int jcnt = (q < 3) ? 76 : 72;
    const int gp = blockIdx.x * 64 + p;

    if (tid < 128) ys[tid] = g_y[blockIdx.x * 128 + tid];
    __syncthreads();
    const float al1 = a1p[0], al2 = a2p[0];

    // L1: 2 -> 300, PReLU
    {
        float y0 = ys[p * 2 + 0], y1 = ys[p * 2 + 1];
        float* row = bufA + p * 301;
        for (int jj = 0; jj < jcnt; jj++) {
            int j = jbase + jj;
            float v = fmaf(y0, w1[j], fmaf(y1, w1[300 + j], b1[j]));
            row[j] = (v >= 0.f) ? v : al1 * v;
        }
    }
    __syncthreads();

    // L2: 300 -> 300, weight streamed in 6 K-chunks of 50
    float acc[76];
#pragma unroll
    for (int t = 0; t < 76; t++) acc[t] = 0.f;
    for (int c = 0; c < 6; c++) {
        for (int i = tid; i < 15000; i += 256) wchunk[i] = w2[c * 15000 + i];
        __syncthreads();
        const float* inrow = bufA + p * 301 + c * 50;
        for (int k = 0; k < 50; k++) {
            float a = inrow[k];
            const float4* wr = reinterpret_cast<const float4*>(wchunk + k * 300 + jbase);
#pragma unroll
            for (int t = 0; t < 19; t++) {
                float4 w = wr[t];
                acc[4 * t + 0] = fmaf(a, w.x, acc[4 * t + 0]);
                acc[4 * t + 1] = fmaf(a, w.y, acc[4 * t + 1]);
                acc[4 * t + 2] = fmaf(a, w.z, acc[4 * t + 2]);
                acc[4 * t + 3] = fmaf(a, w.w, acc[4 * t + 3]);
            }
        }
        __syncthreads();
    }
    {
        float* row = bufB + p * 301;
        for (int jj = 0; jj < jcnt; jj++) {
            int j = jbase + jj;
            float v = acc[jj] + b2[j];
            row[j] = (v >= 0.f) ? v : al2 * v;
        }
    }
    __syncthreads();

    // L3 (300 -> 2) + epilogue: yd, normalize, J^-1 multiply
    if (q == 0) {
        const float* inrow = bufB + p * 301;
        float d0 = b3[0], d1 = b3[1];
        for (int k = 0; k < 300; k++) {
            float h = inrow[k];
            d0 = fmaf(h, w3[k * 2 + 0], d0);
            d1 = fmaf(h, w3[k * 2 + 1], d1);
        }
        float y0 = ys[p * 2 + 0], y1 = ys[p * 2 + 1];
        float lsv = d0 * y0 + d1 * y1;
        float Vy = y0 * y0 + y1 * y1;
        float rl = fmaxf(fmaf(1e-4f, Vy, lsv), 0.f);
        float sc = rl / (Vy + 1e-12f);
        float yd0 = d0 - sc * y0, yd1 = d1 - sc * y1;
        float nrm = sqrtf(yd0 * yd0 + yd1 * yd1);
        float innv = 1.f / fmaxf(nrm, 1e-12f);
        float n0 = yd0 * innv, n1 = yd1 * innv;
        float4 Ji = *reinterpret_cast<const float4*>(g_jinv + gp * 4);
        g_xdh[gp * 2 + 0] = Ji.x * n0 + Ji.y * n1;
        g_xdh[gp * 2 + 1] = Ji.z * n0 + Ji.w * n1;
    }
}

// =================== K3: vel-scalar net + final scaling ====================
__global__ __launch_bounds__(256, 1) void k_vs(
    const float* __restrict__ x,
    const float* __restrict__ w1, const float* __restrict__ b1,
    const float* __restrict__ w2, const float* __restrict__ b2,
    const float* __restrict__ w3, const float* __restrict__ b3,
    float* __restrict__ out) {
    extern __shared__ float sm[];
    float* ws = sm;                   // 10016
    float* bufA = sm + 10016;         // 128*101
    float* bufB = bufA + 128 * 101;   // 128*101
    float* xs = bufB + 128 * 101;     // 256

    const int tid = threadIdx.x;
    const int p = tid >> 1, half = tid & 1;
    const int jbase = half * 52, jcnt = half ? 48 : 52;
    const int gp = blockIdx.x * 128 + p;

    xs[tid] = x[blockIdx.x * 256 + tid];
    for (int i = tid; i < 10016; i += 256) ws[i] = (i < 10000) ? w2[i] : 0.f;
    __syncthreads();

    // L1: 2 -> 100, leaky
    {
        float x0 = xs[p * 2 + 0], x1 = xs[p * 2 + 1];
        float* row = bufA + p * 101;
        for (int jj = 0; jj < jcnt; jj++) {
            int j = jbase + jj;
            float v = fmaf(x0, w1[j], fmaf(x1, w1[100 + j], b1[j]));
            row[j] = (v >= 0.f) ? v : 0.01f * v;
        }
    }
    __syncthreads();

    // L2: 100 -> 100, leaky
    {
        float acc[52];
#pragma unroll
        for (int t = 0; t < 52; t++) acc[t] = 0.f;
        const float* inrow = bufA + p * 101;
        for (int k = 0; k < 100; k++) {
            float a = inrow[k];
            const float4* wr = reinterpret_cast<const float4*>(ws + k * 100 + jbase);
#pragma unroll
            for (int t = 0; t < 13; t++) {
                float4 w = wr[t];
                acc[4 * t + 0] = fmaf(a, w.x, acc[4 * t + 0]);
                acc[4 * t + 1] = fmaf(a, w.y, acc[4 * t + 1]);
                acc[4 * t + 2] = fmaf(a, w.z, acc[4 * t + 2]);
                acc[4 * t + 3] = fmaf(a, w.w, acc[4 * t + 3]);
            }
        }
        float* row = bufB + p * 101;
        for (int jj = 0; jj < jcnt; jj++) {
            float v = acc[jj] + b2[jbase + jj];
            row[jbase + jj] = (v >= 0.f) ? v : 0.01f * v;
        }
    }
    __syncthreads();

    // L3 (100 -> 1) + logv broadcast + exp + multiply
    if (half == 0) {
        const float* inrow = bufB + p * 101;
        float t = b3[0];
        for (int k = 0; k < 100; k++) t = fmaf(inrow[k], w3[k], t);
        float x0 = xs[p * 2 + 0], x1 = xs[p * 2 + 1];
        out[gp * 2 + 0] = (expf(t + x0) + 1e-12f) * g_xdh[gp * 2 + 0];
        out[gp * 2 + 1] = (expf(t + x1) + 1e-12f) * g_xdh[gp * 2 + 1];
    }
}

// ============================== launch =====================================
extern "C" void kernel_launch(void* const* d_in, const int* in_sizes, int n_in,
                              void* d_out, int out_size) {
    const float* x     = (const float*)d_in[0];
    const float* t1w1  = (const float*)d_in[1];
    const float* t1b1  = (const float*)d_in[2];
    const float* t1w2  = (const float*)d_in[3];
    const float* t1b2  = (const float*)d_in[4];
    const float* t1w3  = (const float*)d_in[5];
    const float* t1b3  = (const float*)d_in[6];
    const float* t2w1  = (const float*)d_in[7];
    const float* t2b1  = (const float*)d_in[8];
    const float* t2w2  = (const float*)d_in[9];
    const float* t2b2  = (const float*)d_in[10];
    const float* t2w3  = (const float*)d_in[11];
    const float* t2b3  = (const float*)d_in[12];
    const float* vvw1  = (const float*)d_in[13];
    const float* vvb1  = (const float*)d_in[14];
    const float* vva1  = (const float*)d_in[15];
    const float* vvw2  = (const float*)d_in[16];
    const float* vvb2  = (const float*)d_in[17];
    const float* vva2  = (const float*)d_in[18];
    const float* vvw3  = (const float*)d_in[19];
    const float* vvb3  = (const float*)d_in[20];
    const float* vsw1  = (const float*)d_in[21];
    const float* vsb1  = (const float*)d_in[22];
    const float* vsw2  = (const float*)d_in[23];
    const float* vsb2  = (const float*)d_in[24];
    const float* vsw3  = (const float*)d_in[25];
    const float* vsb3  = (const float*)d_in[26];

    const int SM1 = (10016 + 2 * 192 * 101 + 128 + 384 + 128 + 128 + 256) * 4;  // 199,296 B
    const int SM2 = (15008 + 2 * 64 * 301 + 128) * 4;                           // 214,656 B
    const int SM3 = (10016 + 2 * 128 * 101 + 256) * 4;                          // 144,512 B

    cudaFuncSetAttribute(k_taskmap, cudaFuncAttributeMaxDynamicSharedMemorySize, SM1);
    cudaFuncSetAttribute(k_vv, cudaFuncAttributeMaxDynamicSharedMemorySize, SM2);
    cudaFuncSetAttribute(k_vs, cudaFuncAttributeMaxDynamicSharedMemorySize, SM3);

    k_origin<<<1, 128>>>(t1w1, t1b1, t1w2, t1b2, t1w3, t1b3,
                         t2w1, t2b1, t2w2, t2b2, t2w3, t2b3);
    k_taskmap<<<NPTS / 64, 384, SM1>>>(x, t1w1, t1b1, t1w2, t1b2, t1w3, t1b3,
                                       t2w1, t2b1, t2w2, t2b2, t2w3, t2b3);
    k_vv<<<NPTS / 64, 256, SM2>>>(vvw1, vvb1, vva1, vvw2, vvb2, vva2, vvw3, vvb3);
    k_vs<<<NPTS / 128, 256, SM3>>>(x, vsw1, vsb1, vsw2, vsb2, vsw3, vsb3,
                                   (float*)d_out);
}

// round 4
// speedup vs baseline: 1.1518x; 1.1518x over previous
#include <cuda_runtime.h>
#include <math.h>

#define NPTS 131072

// ------------- global scratch -------------
__device__ float g_origin[2];
__device__ float g_y[NPTS * 2];
__device__ float g_jinv[NPTS * 4];
__device__ float g_xdh[NPTS * 2];

__device__ __forceinline__ float eluf(float v) { return v > 0.f ? v : expm1f(v); }
__device__ __forceinline__ float softplusf(float p) {
    return fmaxf(p, 0.f) + log1pf(expf(-fabsf(p)));
}

#define GEMM_STEP(r, AV, W0, W1)                  \
    acc[r][0] = fmaf(AV, W0.x, acc[r][0]);        \
    acc[r][1] = fmaf(AV, W0.y, acc[r][1]);        \
    acc[r][2] = fmaf(AV, W0.z, acc[r][2]);        \
    acc[r][3] = fmaf(AV, W0.w, acc[r][3]);        \
    acc[r][4] = fmaf(AV, W1.x, acc[r][4]);        \
    acc[r][5] = fmaf(AV, W1.y, acc[r][5]);        \
    acc[r][6] = fmaf(AV, W1.z, acc[r][6]);        \
    acc[r][7] = fmaf(AV, W1.w, acc[r][7]);

// ========================= K0: origin = taskmap(0) =========================
__global__ void k_origin(const float* __restrict__ w1, const float* __restrict__ b1,
                         const float* __restrict__ w2, const float* __restrict__ b2,
                         const float* __restrict__ w3, const float* __restrict__ b3,
                         const float* __restrict__ w4, const float* __restrict__ b4,
                         const float* __restrict__ w5, const float* __restrict__ b5,
                         const float* __restrict__ w6, const float* __restrict__ b6) {
    __shared__ float h[100], h2[100], y1s[2];
    int j = threadIdx.x;
    if (j < 100) h[j] = tanhf(b1[j]);
    __syncthreads();
    if (j < 100) {
        float a = b2[j];
        for (int k = 0; k < 100; k++) a = fmaf(h[k], w2[k * 100 + j], a);
        h2[j] = tanhf(a);
    }
    __syncthreads();
    if (j < 2) {
        float a = b3[j];
        for (int k = 0; k < 100; k++) a = fmaf(h2[k], w3[k * 2 + j], a);
        y1s[j] = a;
    }
    __syncthreads();
    if (j < 100) {
        float a = fmaf(y1s[0], w4[j], fmaf(y1s[1], w4[100 + j], b4[j]));
        h[j] = eluf(a);
    }
    __syncthreads();
    if (j < 100) {
        float a = b5[j];
        for (int k = 0; k < 100; k++) a = fmaf(h[k], w5[k * 100 + j], a);
        h2[j] = eluf(a);
    }
    __syncthreads();
    if (j < 2) {
        float a = b6[j];
        for (int k = 0; k < 100; k++) a = fmaf(h2[k], w6[k * 2 + j], a);
        float s = softplusf(a);
        g_origin[j] = (1.f + s) * y1s[j];
    }
}

// ========================= K1: taskmap + Jacobian ==========================
// 64 points/block, 192 rows (value, tan0, tan1). 320 threads; GEMM threads:
// tid<312, rg=tid/13 (8 rows each), og=tid%13 (8 outs each, padded to 104).
// Buffer row stride 108 floats (16B aligned).
template <int ACT>  // 0 = tanh, 1 = elu
__device__ __forceinline__ void tm_mid(const float* __restrict__ W, const float* __restrict__ b,
                                       float* ws, float* bp, const float* inb, float* outb,
                                       int tid, bool active, int rg, int og) {
    // stage weights padded to 104 cols + padded bias
    for (int i = tid; i < 10400; i += 320) {
        int k = i / 104, j = i % 104;
        ws[i] = (j < 100) ? W[k * 100 + j] : 0.f;
    }
    if (tid < 104) bp[tid] = (tid < 100) ? b[tid] : 0.f;
    __syncthreads();

    const int row0 = rg * 8;
    const int jb = og * 8;
    const int comp = rg >> 3;

    float acc[8][8];
#pragma unroll
    for (int r = 0; r < 8; r++)
#pragma unroll
        for (int q = 0; q < 8; q++) acc[r][q] = 0.f;

    if (active) {
        for (int k = 0; k < 100; k += 4) {
            float4 wA0 = *(const float4*)(ws + (k + 0) * 104 + jb);
            float4 wA1 = *(const float4*)(ws + (k + 0) * 104 + jb + 4);
            float4 wB0 = *(const float4*)(ws + (k + 1) * 104 + jb);
            float4 wB1 = *(const float4*)(ws + (k + 1) * 104 + jb + 4);
            float4 wC0 = *(const float4*)(ws + (k + 2) * 104 + jb);
            float4 wC1 = *(const float4*)(ws + (k + 2) * 104 + jb + 4);
            float4 wD0 = *(const float4*)(ws + (k + 3) * 104 + jb);
            float4 wD1 = *(const float4*)(ws + (k + 3) * 104 + jb + 4);
#pragma unroll
            for (int r = 0; r < 8; r++) {
                float4 a = *(const float4*)(inb + (row0 + r) * 108 + k);
                GEMM_STEP(r, a.x, wA0, wA1)
                GEMM_STEP(r, a.y, wB0, wB1)
                GEMM_STEP(r, a.z, wC0, wC1)
                GEMM_STEP(r, a.w, wD0, wD1)
            }
        }
    }
    // value rows: activate + write
    if (active && comp == 0) {
#pragma unroll
        for (int r = 0; r < 8; r++)
#pragma unroll
            for (int q = 0; q < 8; q++) {
                float v = acc[r][q] + bp[jb + q];
                outb[(row0 + r) * 108 + jb + q] = (ACT == 0) ? tanhf(v) : eluf(v);
            }
    }
    __syncthreads();
    // tangent rows: scale raw acc by activation derivative of value row
    if (active && comp != 0) {
        const int pbase = row0 - comp * 64;
#pragma unroll
        for (int r = 0; r < 8; r++)
#pragma unroll
            for (int q = 0; q < 8; q++) {
                float h = outb[(pbase + r) * 108 + jb + q];
                float d = (ACT == 0) ? (1.f - h * h) : (h > 0.f ? 1.f : h + 1.f);
                outb[(row0 + r) * 108 + jb + q] = acc[r][q] * d;
            }
    }
    __syncthreads();
}

__global__ __launch_bounds__(320, 1) void k_taskmap(
    const float* __restrict__ x,
    const float* __restrict__ w1, const float* __restrict__ b1,
    const float* __restrict__ w2, const float* __restrict__ b2,
    const float* __restrict__ w3, const float* __restrict__ b3,
    const float* __restrict__ w4, const float* __restrict__ b4,
    const float* __restrict__ w5, const float* __restrict__ b5,
    const float* __restrict__ w6, const float* __restrict__ b6) {
    extern __shared__ float sm[];
    float* ws   = sm;                  // 10400
    float* bufA = ws + 10400;          // 192*108 = 20736
    float* bufB = bufA + 20736;        // 20736
    float* xs   = bufB + 20736;        // 128
    float* v2   = xs + 128;            // 384
    float* ss   = v2 + 384;            // 128
    float* sg   = ss + 128;            // 128
    float* Jsh  = sg + 128;            // 256
    float* accb = Jsh + 256;           // 384
    float* bp   = accb + 384;          // 104

    const int tid = threadIdx.x;
    const bool active = tid < 312;
    const int rg = tid / 13;
    const int og = tid % 13;
    const int gbase = blockIdx.x * 64;

    if (tid < 128) xs[tid] = x[blockIdx.x * 128 + tid];
    __syncthreads();

    // ---- tm1 L1 (2 -> 100, tanh); value then tangent ----
    for (int i = tid; i < 6400; i += 320) {
        int p = i / 100, j = i % 100;
        float h = tanhf(fmaf(xs[p * 2], w1[j], fmaf(xs[p * 2 + 1], w1[100 + j], b1[j])));
        bufA[p * 108 + j] = h;
    }
    __syncthreads();
    for (int i = tid; i < 12800; i += 320) {
        int c = i / 6400, rem = i % 6400, p = rem / 100, j = rem % 100;
        float h = bufA[p * 108 + j];
        bufA[(64 + c * 64 + p) * 108 + j] = w1[c * 100 + j] * (1.f - h * h);
    }
    __syncthreads();

    // ---- tm1 L2 (100x100, tanh) ----
    tm_mid<0>(w2, b2, ws, bp, bufA, bufB, tid, active, rg, og);

    // ---- tm1 L3 (100 -> 2) + residual / identity ----
    for (int t = tid; t < 384; t += 320) {
        int r = t >> 1, h = t & 1;
        const float* row = bufB + r * 108;
        float a0 = 0.f, a1 = 0.f, a2 = 0.f, a3 = 0.f;
        for (int k = 0; k < 100; k += 4) {
            a0 = fmaf(row[k + 0], w3[(k + 0) * 2 + h], a0);
            a1 = fmaf(row[k + 1], w3[(k + 1) * 2 + h], a1);
            a2 = fmaf(row[k + 2], w3[(k + 2) * 2 + h], a2);
            a3 = fmaf(row[k + 3], w3[(k + 3) * 2 + h], a3);
        }
        float acc = (a0 + a1) + (a2 + a3);
        int cmp = r / 64, p = r % 64;
        float val;
        if (cmp == 0) val = acc + b3[h] + xs[p * 2 + h];
        else val = acc + (((cmp - 1) == h) ? 1.f : 0.f);
        v2[r * 2 + h] = val;
    }
    __syncthreads();

    // ---- tm2 L1 (2 -> 100, elu); value then tangent ----
    for (int i = tid; i < 6400; i += 320) {
        int p = i / 100, j = i % 100;
        float a = fmaf(v2[p * 2], w4[j], fmaf(v2[p * 2 + 1], w4[100 + j], b4[j]));
        bufA[p * 108 + j] = eluf(a);
    }
    __syncthreads();
    for (int i = tid; i < 12800; i += 320) {
        int c = i / 6400, rem = i % 6400, p = rem / 100, j = rem % 100;
        int r = 64 + c * 64 + p;
        float raw = fmaf(v2[r * 2], w4[j], v2[r * 2 + 1] * w4[100 + j]);
        float h = bufA[p * 108 + j];
        bufA[r * 108 + j] = raw * (h > 0.f ? 1.f : h + 1.f);
    }
    __syncthreads();

    // ---- tm2 L2 (100x100, elu) ----
    tm_mid<1>(w5, b5, ws, bp, bufA, bufB, tid, active, rg, og);

    // ---- tm2 L3 (100 -> 2) + softplus gate + y + J + pinv ----
    for (int t = tid; t < 384; t += 320) {
        int r = t >> 1, h = t & 1;
        const float* row = bufB + r * 108;
        float a0 = 0.f, a1 = 0.f, a2 = 0.f, a3 = 0.f;
        for (int k = 0; k < 100; k += 4) {
            a0 = fmaf(row[k + 0], w6[(k + 0) * 2 + h], a0);
            a1 = fmaf(row[k + 1], w6[(k + 1) * 2 + h], a1);
            a2 = fmaf(row[k + 2], w6[(k + 2) * 2 + h], a2);
            a3 = fmaf(row[k + 3], w6[(k + 3) * 2 + h], a3);
        }
        float acc = (a0 + a1) + (a2 + a3);
        accb[t] = acc;
        if (r < 64) {  // value rows
            float pv = acc + b6[h];
            float s = softplusf(pv);
            ss[r * 2 + h] = s;
            sg[r * 2 + h] = 1.f / (1.f + expf(-pv));
            g_y[(gbase + r) * 2 + h] = (1.f + s) * v2[r * 2 + h] - g_origin[h];
        }
    }
    __syncthreads();
    for (int t = tid; t < 384; t += 320) {
        int r = t >> 1, i = t & 1;
        if (r >= 64) {
            int c = r / 64 - 1, p = r % 64;
            float acc = accb[t];
            float s = ss[p * 2 + i];
            float ds = sg[p * 2 + i] * acc;
            Jsh[p * 4 + i * 2 + c] = fmaf(ds, v2[p * 2 + i], (1.f + s) * v2[r * 2 + i]);
        }
    }
    __syncthreads();
    if (tid < 64) {
        int p = tid, gp = gbase + p;
        float a = Jsh[p * 4 + 0], b_ = Jsh[p * 4 + 1];
        float c = Jsh[p * 4 + 2], d = Jsh[p * 4 + 3];
        float det = a * d - b_ * c;
        float n2 = a * a + b_ * b_ + c * c + d * d;
        float ia, ib, ic, id;
        if (fabsf(det) > 1e-10f * n2) {
            float inv = 1.f / det;
            ia = d * inv; ib = -b_ * inv; ic = -c * inv; id = a * inv;
        } else {
            float inv = (n2 > 0.f) ? 1.f / n2 : 0.f;
            ia = a * inv; ib = c * inv; ic = b_ * inv; id = d * inv;
        }
        float4 o; o.x = ia; o.y = ib; o.z = ic; o.w = id;
        *reinterpret_cast<float4*>(g_jinv + gp * 4) = o;
    }
}

// ====================== K2: vv net + yd + J^-1 * yd_n ======================
// 64 points/block. 320 threads; GEMM threads: tid<304, rg=tid/38 (8 pts),
// og=tid%38 (8 outs, padded to 304). bufA stride 308. L3 fused via partial dots.
__global__ __launch_bounds__(320, 1) void k_vv(
    const float* __restrict__ w1, const float* __restrict__ b1, const float* __restrict__ a1p,
    const float* __restrict__ w2, const float* __restrict__ b2, const float* __restrict__ a2p,
    const float* __restrict__ w3, const float* __restrict__ b3) {
    extern __shared__ float sm[];
    float* ws   = sm;                  // 100*304 = 30400
    float* bufA = ws + 30400;          // 64*308 = 19712
    float* ys   = bufA + 19712;        // 128
    float* b2p  = ys + 128;            // 304
    float* w3p  = b2p + 304;           // 608
    float* dsum = w3p + 608;           // 128

    const int tid = threadIdx.x;
    const bool active = tid < 304;
    const int rg = tid / 38;
    const int og = tid % 38;
    const int row0 = rg * 8;
    const int jb = og * 8;
    const int gbase = blockIdx.x * 64;

    if (tid < 128) ys[tid] = g_y[blockIdx.x * 128 + tid];
    for (int i = tid; i < 304; i += 320) b2p[i] = (i < 300) ? b2[i] : 0.f;
    for (int i = tid; i < 608; i += 320) w3p[i] = (i < 600) ? w3[i] : 0.f;
    if (tid < 128) dsum[tid] = b3[tid & 1];
    const float al1 = a1p[0], al2 = a2p[0];
    __syncthreads();

    // L1: 2 -> 300, PReLU
    for (int i = tid; i < 19200; i += 320) {
        int p = i / 300, j = i % 300;
        float v = fmaf(ys[p * 2], w1[j], fmaf(ys[p * 2 + 1], w1[300 + j], b1[j]));
        bufA[p * 308 + j] = (v >= 0.f) ? v : al1 * v;
    }
    __syncthreads();

    // L2: 300x300 GEMM, 3 K-chunks of 100
    float acc[8][8];
#pragma unroll
    for (int r = 0; r < 8; r++)
#pragma unroll
        for (int q = 0; q < 8; q++) acc[r][q] = 0.f;

    for (int c = 0; c < 3; c++) {
        for (int i = tid; i < 30400; i += 320) {
            int kk = i / 304, j = i % 304;
            ws[i] = (j < 300) ? w2[(c * 100 + kk) * 300 + j] : 0.f;
        }
        __syncthreads();
        if (active) {
            const int kb = c * 100;
            for (int k = 0; k < 100; k += 4) {
                float4 wA0 = *(const float4*)(ws + (k + 0) * 304 + jb);
                float4 wA1 = *(const float4*)(ws + (k + 0) * 304 + jb + 4);
                float4 wB0 = *(const float4*)(ws + (k + 1) * 304 + jb);
                float4 wB1 = *(const float4*)(ws + (k + 1) * 304 + jb + 4);
                float4 wC0 = *(const float4*)(ws + (k + 2) * 304 + jb);
                float4 wC1 = *(const float4*)(ws + (k + 2) * 304 + jb + 4);
                float4 wD0 = *(const float4*)(ws + (k + 3) * 304 + jb);
                float4 wD1 = *(const float4*)(ws + (k + 3) * 304 + jb + 4);
#pragma unroll
                for (int r = 0; r < 8; r++) {
                    float4 a = *(const float4*)(bufA + (row0 + r) * 308 + kb + k);
                    GEMM_STEP(r, a.x, wA0, wA1)
                    GEMM_STEP(r, a.y, wB0, wB1)
                    GEMM_STEP(r, a.z, wC0, wC1)
                    GEMM_STEP(r, a.w, wD0, wD1)
                }
            }
        }
        __syncthreads();
    }

    // PReLU + fused L3 partial dots
    if (active) {
#pragma unroll
        for (int r = 0; r < 8; r++) {
            float d0 = 0.f, d1 = 0.f;
#pragma unroll
            for (int q = 0; q < 8; q++) {
                int j = jb + q;
                float h = acc[r][q] + b2p[j];
                h = (h >= 0.f) ? h : al2 * h;
                d0 = fmaf(h, w3p[j * 2 + 0], d0);
                d1 = fmaf(h, w3p[j * 2 + 1], d1);
            }
            atomicAdd(&dsum[(row0 + r) * 2 + 0], d0);
            atomicAdd(&dsum[(row0 + r) * 2 + 1], d1);
        }
    }
    __syncthreads();

    // epilogue per point
    if (tid < 64) {
        int p = tid, gp = gbase + p;
        float d0 = dsum[p * 2 + 0], d1 = dsum[p * 2 + 1];
        float y0 = ys[p * 2 + 0], y1 = ys[p * 2 + 1];
        float lsv = d0 * y0 + d1 * y1;
        float Vy = y0 * y0 + y1 * y1;
        float rl = fmaxf(fmaf(1e-4f, Vy, lsv), 0.f);
        float sc = rl / (Vy + 1e-12f);
        float yd0 = d0 - sc * y0, yd1 = d1 - sc * y1;
        float nrm = sqrtf(yd0 * yd0 + yd1 * yd1);
        float innv = 1.f / fmaxf(nrm, 1e-12f);
        float n0 = yd0 * innv, n1 = yd1 * innv;
        float4 Ji = *reinterpret_cast<const float4*>(g_jinv + gp * 4);
        g_xdh[gp * 2 + 0] = Ji.x * n0 + Ji.y * n1;
        g_xdh[gp * 2 + 1] = Ji.z * n0 + Ji.w * n1;
    }
}

// =================== K3: vel-scalar net + final scaling ====================
// 128 points/block. 224 threads; GEMM threads: tid<208, rg=tid/13 (8 pts),
// og=tid%13 (8 outs, padded to 104). 2 CTAs/SM.
__global__ __launch_bounds__(224, 2) void k_vs(
    const float* __restrict__ x,
    const float* __restrict__ w1, const float* __restrict__ b1,
    const float* __restrict__ w2, const float* __restrict__ b2,
    const float* __restrict__ w3, const float* __restrict__ b3,
    float* __restrict__ out) {
    extern __shared__ float sm[];
    float* ws   = sm;                  // 100*104 = 10400
    float* bufA = ws + 10400;          // 128*108 = 13824
    float* xs   = bufA + 13824;        // 256
    float* b2p  = xs + 256;            // 104
    float* w3p  = b2p + 104;           // 104
    float* dsum = w3p + 104;           // 128

    const int tid = threadIdx.x;
    const bool active = tid < 208;
    const int rg = tid / 13;
    const int og = tid % 13;
    const int row0 = rg * 8;
    const int jb = og * 8;
    const int gbase = blockIdx.x * 128;

    for (int i = tid; i < 256; i += 224) xs[i] = x[blockIdx.x * 256 + i];
    for (int i = tid; i < 10400; i += 224) {
        int k = i / 104, j = i % 104;
        ws[i] = (j < 100) ? w2[k * 100 + j] : 0.f;
    }
    if (tid < 104) {
        b2p[tid] = (tid < 100) ? b2[tid] : 0.f;
        w3p[tid] = (tid < 100) ? w3[tid] : 0.f;
    }
    if (tid < 128) dsum[tid] = b3[0];
    __syncthreads();

    // L1: 2 -> 100, leaky
    for (int i = tid; i < 12800; i += 224) {
        int p = i / 100, j = i % 100;
        float v = fmaf(xs[p * 2], w1[j], fmaf(xs[p * 2 + 1], w1[100 + j], b1[j]));
        bufA[p * 108 + j] = (v >= 0.f) ? v : 0.01f * v;
    }
    __syncthreads();

    // L2: 100x100 GEMM
    float acc[8][8];
#pragma unroll
    for (int r = 0; r < 8; r++)
#pragma unroll
        for (int q = 0; q < 8; q++) acc[r][q] = 0.f;
    if (active) {
        for (int k = 0; k < 100; k += 4) {
            float4 wA0 = *(const float4*)(ws + (k + 0) * 104 + jb);
            float4 wA1 = *(const float4*)(ws + (k + 0) * 104 + jb + 4);
            float4 wB0 = *(const float4*)(ws + (k + 1) * 104 + jb);
            float4 wB1 = *(const float4*)(ws + (k + 1) * 104 + jb + 4);
            float4 wC0 = *(const float4*)(ws + (k + 2) * 104 + jb);
            float4 wC1 = *(const float4*)(ws + (k + 2) * 104 + jb + 4);
            float4 wD0 = *(const float4*)(ws + (k + 3) * 104 + jb);
            float4 wD1 = *(const float4*)(ws + (k + 3) * 104 + jb + 4);
#pragma unroll
            for (int r = 0; r < 8; r++) {
                float4 a = *(const float4*)(bufA + (row0 + r) * 108 + k);
                GEMM_STEP(r, a.x, wA0, wA1)
                GEMM_STEP(r, a.y, wB0, wB1)
                GEMM_STEP(r, a.z, wC0, wC1)
                GEMM_STEP(r, a.w, wD0, wD1)
            }
        }
        // leaky + fused L3 partial dots (100 -> 1)
#pragma unroll
        for (int r = 0; r < 8; r++) {
            float dp = 0.f;
#pragma unroll
            for (int q = 0; q < 8; q++) {
                int j = jb + q;
                float h = acc[r][q] + b2p[j];
                h = (h >= 0.f) ? h : 0.01f * h;
                dp = fmaf(h, w3p[j], dp);
            }
            atomicAdd(&dsum[row0 + r], dp);
        }
    }
    __syncthreads();

    // final: exp(logv) * xd_hat
    if (tid < 128) {
        int p = tid, gp = gbase + p;
        float t = dsum[p];
        float x0 = xs[p * 2 + 0], x1 = xs[p * 2 + 1];
        out[gp * 2 + 0] = (expf(t + x0) + 1e-12f) * g_xdh[gp * 2 + 0];
        out[gp * 2 + 1] = (expf(t + x1) + 1e-12f) * g_xdh[gp * 2 + 1];
    }
}

// ============================== launch =====================================
extern "C" void kernel_launch(void* const* d_in, const int* in_sizes, int n_in,
                              void* d_out, int out_size) {
    const float* x     = (const float*)d_in[0];
    const float* t1w1  = (const float*)d_in[1];
    const float* t1b1  = (const float*)d_in[2];
    const float* t1w2  = (const float*)d_in[3];
    const float* t1b2  = (const float*)d_in[4];
    const float* t1w3  = (const float*)d_in[5];
    const float* t1b3  = (const float*)d_in[6];
    const float* t2w1  = (const float*)d_in[7];
    const float* t2b1  = (const float*)d_in[8];
    const float* t2w2  = (const float*)d_in[9];
    const float* t2b2  = (const float*)d_in[10];
    const float* t2w3  = (const float*)d_in[11];
    const float* t2b3  = (const float*)d_in[12];
    const float* vvw1  = (const float*)d_in[13];
    const float* vvb1  = (const float*)d_in[14];
    const float* vva1  = (const float*)d_in[15];
    const float* vvw2  = (const float*)d_in[16];
    const float* vvb2  = (const float*)d_in[17];
    const float* vva2  = (const float*)d_in[18];
    const float* vvw3  = (const float*)d_in[19];
    const float* vvb3  = (const float*)d_in[20];
    const float* vsw1  = (const float*)d_in[21];
    const float* vsb1  = (const float*)d_in[22];
    const float* vsw2  = (const float*)d_in[23];
    const float* vsb2  = (const float*)d_in[24];
    const float* vsw3  = (const float*)d_in[25];
    const float* vsb3  = (const float*)d_in[26];

    const int SM1 = (10400 + 2 * 20736 + 128 + 384 + 128 + 128 + 256 + 384 + 104) * 4;  // 213,536
    const int SM2 = (30400 + 19712 + 128 + 304 + 608 + 128) * 4;                        // 205,120
    const int SM3 = (10400 + 13824 + 256 + 104 + 104 + 128) * 4;                        //  99,264

    cudaFuncSetAttribute(k_taskmap, cudaFuncAttributeMaxDynamicSharedMemorySize, SM1);
    cudaFuncSetAttribute(k_vv, cudaFuncAttributeMaxDynamicSharedMemorySize, SM2);
    cudaFuncSetAttribute(k_vs, cudaFuncAttributeMaxDynamicSharedMemorySize, SM3);

    k_origin<<<1, 128>>>(t1w1, t1b1, t1w2, t1b2, t1w3, t1b3,
                         t2w1, t2b1, t2w2, t2b2, t2w3, t2b3);
    k_taskmap<<<NPTS / 64, 320, SM1>>>(x, t1w1, t1b1, t1w2, t1b2, t1w3, t1b3,
                                       t2w1, t2b1, t2w2, t2b2, t2w3, t2b3);
    k_vv<<<NPTS / 64, 320, SM2>>>(vvw1, vvb1, vva1, vvw2, vvb2, vva2, vvw3, vvb3);
    k_vs<<<NPTS / 128, 224, SM3>>>(x, vsw1, vsb1, vsw2, vsb2, vsw3, vsb3,
                                   (float*)d_out);
}

// round 5
// speedup vs baseline: 1.2253x; 1.0638x over previous
#include <cuda_runtime.h>
#include <math.h>

#define NPTS 131072

typedef unsigned long long ull;

// ------------- global scratch -------------
__device__ float g_origin[2];
__device__ float g_y[NPTS * 2];
__device__ float g_jinv[NPTS * 4];
__device__ float g_xdh[NPTS * 2];

__device__ __forceinline__ float eluf(float v) { return v > 0.f ? v : expm1f(v); }
__device__ __forceinline__ float softplusf(float p) {
    return fmaxf(p, 0.f) + log1pf(expf(-fabsf(p)));
}

// ---- packed f32x2 helpers (Blackwell FFMA2 via PTX fma.rn.f32x2) ----
__device__ __forceinline__ ull pk2(float a, float b) {
    ull r; asm("mov.b64 %0,{%1,%2};" : "=l"(r) : "f"(a), "f"(b)); return r;
}
__device__ __forceinline__ ull bc2(float a) { return pk2(a, a); }
__device__ __forceinline__ void upk2(ull v, float& a, float& b) {
    asm("mov.b64 {%0,%1},%2;" : "=f"(a), "=f"(b) : "l"(v));
}
__device__ __forceinline__ void fma2(ull& d, ull a, ull b) {
    asm("fma.rn.f32x2 %0, %1, %2, %0;" : "+l"(d) : "l"(a), "l"(b));
}

#define GS2(r, AB, U0, U1)            \
    fma2(acc[r][0], AB, U0.x);        \
    fma2(acc[r][1], AB, U0.y);        \
    fma2(acc[r][2], AB, U1.x);        \
    fma2(acc[r][3], AB, U1.y);

// ========================= K0: origin = taskmap(0) =========================
__global__ void k_origin(const float* __restrict__ w1, const float* __restrict__ b1,
                         const float* __restrict__ w2, const float* __restrict__ b2,
                         const float* __restrict__ w3, const float* __restrict__ b3,
                         const float* __restrict__ w4, const float* __restrict__ b4,
                         const float* __restrict__ w5, const float* __restrict__ b5,
                         const float* __restrict__ w6, const float* __restrict__ b6) {
    __shared__ float h[100], h2[100], y1s[2];
    int j = threadIdx.x;
    if (j < 100) h[j] = tanhf(b1[j]);
    __syncthreads();
    if (j < 100) {
        float a = b2[j];
        for (int k = 0; k < 100; k++) a = fmaf(h[k], w2[k * 100 + j], a);
        h2[j] = tanhf(a);
    }
    __syncthreads();
    if (j < 2) {
        float a = b3[j];
        for (int k = 0; k < 100; k++) a = fmaf(h2[k], w3[k * 2 + j], a);
        y1s[j] = a;
    }
    __syncthreads();
    if (j < 100) {
        float a = fmaf(y1s[0], w4[j], fmaf(y1s[1], w4[100 + j], b4[j]));
        h[j] = eluf(a);
    }
    __syncthreads();
    if (j < 100) {
        float a = b5[j];
        for (int k = 0; k < 100; k++) a = fmaf(h[k], w5[k * 100 + j], a);
        h2[j] = eluf(a);
    }
    __syncthreads();
    if (j < 2) {
        float a = b6[j];
        for (int k = 0; k < 100; k++) a = fmaf(h2[k], w6[k * 2 + j], a);
        float s = softplusf(a);
        g_origin[j] = (1.f + s) * y1s[j];
    }
}

// ========================= K1: taskmap + Jacobian ==========================
template <int ACT>  // 0 = tanh, 1 = elu
__device__ __forceinline__ void tm_mid(const float* __restrict__ W, const float* __restrict__ b,
                                       float* ws, float* bp, const float* inb, float* outb,
                                       int tid, bool active, int rg, int og) {
    for (int i = tid; i < 10400; i += 320) {
        int k = i / 104, j = i % 104;
        ws[i] = (j < 100) ? W[k * 100 + j] : 0.f;
    }
    if (tid < 104) bp[tid] = (tid < 100) ? b[tid] : 0.f;
    __syncthreads();

    const int row0 = rg * 8;
    const int jb = og * 8;
    const int comp = rg >> 3;

    ull acc[8][4];
#pragma unroll
    for (int r = 0; r < 8; r++)
#pragma unroll
        for (int q = 0; q < 4; q++) acc[r][q] = 0ULL;

    if (active) {
        for (int k = 0; k < 100; k += 4) {
            ulonglong2 wA0 = *(const ulonglong2*)(ws + (k + 0) * 104 + jb);
            ulonglong2 wA1 = *(const ulonglong2*)(ws + (k + 0) * 104 + jb + 4);
            ulonglong2 wB0 = *(const ulonglong2*)(ws + (k + 1) * 104 + jb);
            ulonglong2 wB1 = *(const ulonglong2*)(ws + (k + 1) * 104 + jb + 4);
            ulonglong2 wC0 = *(const ulonglong2*)(ws + (k + 2) * 104 + jb);
            ulonglong2 wC1 = *(const ulonglong2*)(ws + (k + 2) * 104 + jb + 4);
            ulonglong2 wD0 = *(const ulonglong2*)(ws + (k + 3) * 104 + jb);
            ulonglong2 wD1 = *(const ulonglong2*)(ws + (k + 3) * 104 + jb + 4);
#pragma unroll
            for (int r = 0; r < 8; r++) {
                float4 a = *(const float4*)(inb + (row0 + r) * 108 + k);
                GS2(r, bc2(a.x), wA0, wA1)
                GS2(r, bc2(a.y), wB0, wB1)
                GS2(r, bc2(a.z), wC0, wC1)
                GS2(r, bc2(a.w), wD0, wD1)
            }
        }
    }
    if (active && comp == 0) {
#pragma unroll
        for (int r = 0; r < 8; r++)
#pragma unroll
            for (int q = 0; q < 4; q++) {
                float v0, v1; upk2(acc[r][q], v0, v1);
                v0 += bp[jb + 2 * q];
                v1 += bp[jb + 2 * q + 1];
                outb[(row0 + r) * 108 + jb + 2 * q]     = (ACT == 0) ? tanhf(v0) : eluf(v0);
                outb[(row0 + r) * 108 + jb + 2 * q + 1] = (ACT == 0) ? tanhf(v1) : eluf(v1);
            }
    }
    __syncthreads();
    if (active && comp != 0) {
        const int pbase = row0 - comp * 64;
#pragma unroll
        for (int r = 0; r < 8; r++)
#pragma unroll
            for (int q = 0; q < 4; q++) {
                float v0, v1; upk2(acc[r][q], v0, v1);
                float h0 = outb[(pbase + r) * 108 + jb + 2 * q];
                float h1 = outb[(pbase + r) * 108 + jb + 2 * q + 1];
                float d0 = (ACT == 0) ? (1.f - h0 * h0) : (h0 > 0.f ? 1.f : h0 + 1.f);
                float d1 = (ACT == 0) ? (1.f - h1 * h1) : (h1 > 0.f ? 1.f : h1 + 1.f);
                outb[(row0 + r) * 108 + jb + 2 * q]     = v0 * d0;
                outb[(row0 + r) * 108 + jb + 2 * q + 1] = v1 * d1;
            }
    }
    __syncthreads();
}

__global__ __launch_bounds__(320, 1) void k_taskmap(
    const float* __restrict__ x,
    const float* __restrict__ w1, const float* __restrict__ b1,
    const float* __restrict__ w2, const float* __restrict__ b2,
    const float* __restrict__ w3, const float* __restrict__ b3,
    const float* __restrict__ w4, const float* __restrict__ b4,
    const float* __restrict__ w5, const float* __restrict__ b5,
    const float* __restrict__ w6, const float* __restrict__ b6) {
    extern __shared__ float sm[];
    float* ws   = sm;                  // 10400
    float* bufA = ws + 10400;          // 192*108 = 20736
    float* bufB = bufA + 20736;        // 20736
    float* xs   = bufB + 20736;        // 128
    float* v2   = xs + 128;            // 384
    float* ss   = v2 + 384;            // 128
    float* sg   = ss + 128;            // 128
    float* Jsh  = sg + 128;            // 256
    float* accb = Jsh + 256;           // 384
    float* bp   = accb + 384;          // 104  (cum 53384, even)
    ull* w3u    = (ull*)(bp + 104);    // 100 ull = 200 floats
    ull* w6u    = (ull*)(bp + 304);    // 100 ull = 200 floats

    const int tid = threadIdx.x;
    const bool active = tid < 312;
    const int rg = tid / 13;
    const int og = tid % 13;
    const int gbase = blockIdx.x * 64;

    if (tid < 128) xs[tid] = x[blockIdx.x * 128 + tid];
    if (tid >= 128 && tid < 228) w3u[tid - 128] = ((const ull*)w3)[tid - 128];
    if (tid >= 228 && tid < 320 + 8) { }
    if (tid >= 228 && tid < 320) w6u[tid - 228] = ((const ull*)w6)[tid - 228];
    if (tid < 8) w6u[92 + tid] = ((const ull*)w6)[92 + tid];
    __syncthreads();

    // ---- tm1 L1 (2 -> 100, tanh); value then tangent ----
    for (int i = tid; i < 6400; i += 320) {
        int p = i / 100, j = i % 100;
        float h = tanhf(fmaf(xs[p * 2], w1[j], fmaf(xs[p * 2 + 1], w1[100 + j], b1[j])));
        bufA[p * 108 + j] = h;
    }
    __syncthreads();
    for (int i = tid; i < 12800; i += 320) {
        int c = i / 6400, rem = i % 6400, p = rem / 100, j = rem % 100;
        float h = bufA[p * 108 + j];
        bufA[(64 + c * 64 + p) * 108 + j] = w1[c * 100 + j] * (1.f - h * h);
    }
    __syncthreads();

    // ---- tm1 L2 (100x100, tanh) ----
    tm_mid<0>(w2, b2, ws, bp, bufA, bufB, tid, active, rg, og);

    // ---- tm1 L3 (100 -> 2) packed, + residual / identity ----
    if (tid < 192) {
        int r = tid;
        const float* row = bufB + r * 108;
        ull a2 = 0ULL, a2b = 0ULL;
        for (int k = 0; k < 100; k += 4) {
            fma2(a2,  bc2(row[k + 0]), w3u[k + 0]);
            fma2(a2b, bc2(row[k + 1]), w3u[k + 1]);
            fma2(a2,  bc2(row[k + 2]), w3u[k + 2]);
            fma2(a2b, bc2(row[k + 3]), w3u[k + 3]);
        }
        float A0, A1, B0, B1; upk2(a2, A0, A1); upk2(a2b, B0, B1);
        A0 += B0; A1 += B1;
        int cmp = r / 64, p = r % 64;
        if (cmp == 0) {
            v2[r * 2 + 0] = A0 + b3[0] + xs[p * 2 + 0];
            v2[r * 2 + 1] = A1 + b3[1] + xs[p * 2 + 1];
        } else {
            v2[r * 2 + 0] = A0 + ((cmp - 1) == 0 ? 1.f : 0.f);
            v2[r * 2 + 1] = A1 + ((cmp - 1) == 1 ? 1.f : 0.f);
        }
    }
    __syncthreads();

    // ---- tm2 L1 (2 -> 100, elu); value then tangent ----
    for (int i = tid; i < 6400; i += 320) {
        int p = i / 100, j = i % 100;
        float a = fmaf(v2[p * 2], w4[j], fmaf(v2[p * 2 + 1], w4[100 + j], b4[j]));
        bufA[p * 108 + j] = eluf(a);
    }
    __syncthreads();
    for (int i = tid; i < 12800; i += 320) {
        int c = i / 6400, rem = i % 6400, p = rem / 100, j = rem % 100;
        int r = 64 + c * 64 + p;
        float raw = fmaf(v2[r * 2], w4[j], v2[r * 2 + 1] * w4[100 + j]);
        float h = bufA[p * 108 + j];
        bufA[r * 108 + j] = raw * (h > 0.f ? 1.f : h + 1.f);
    }
    __syncthreads();

    // ---- tm2 L2 (100x100, elu) ----
    tm_mid<1>(w5, b5, ws, bp, bufA, bufB, tid, active, rg, og);

    // ---- tm2 L3 (100 -> 2) packed + softplus gate + y + J + pinv ----
    if (tid < 192) {
        int r = tid;
        const float* row = bufB + r * 108;
        ull a2 = 0ULL, a2b = 0ULL;
        for (int k = 0; k < 100; k += 4) {
            fma2(a2,  bc2(row[k + 0]), w6u[k + 0]);
            fma2(a2b, bc2(row[k + 1]), w6u[k + 1]);
            fma2(a2,  bc2(row[k + 2]), w6u[k + 2]);
            fma2(a2b, bc2(row[k + 3]), w6u[k + 3]);
        }
        float A0, A1, B0, B1; upk2(a2, A0, A1); upk2(a2b, B0, B1);
        A0 += B0; A1 += B1;
        if (r < 64) {
            float pv0 = A0 + b6[0], pv1 = A1 + b6[1];
            float s0 = softplusf(pv0), s1 = softplusf(pv1);
            ss[r * 2 + 0] = s0; ss[r * 2 + 1] = s1;
            sg[r * 2 + 0] = 1.f / (1.f + expf(-pv0));
            sg[r * 2 + 1] = 1.f / (1.f + expf(-pv1));
            g_y[(gbase + r) * 2 + 0] = (1.f + s0) * v2[r * 2 + 0] - g_origin[0];
            g_y[(gbase + r) * 2 + 1] = (1.f + s1) * v2[r * 2 + 1] - g_origin[1];
        } else {
            accb[r * 2 + 0] = A0;
            accb[r * 2 + 1] = A1;
        }
    }
    __syncthreads();
    if (tid < 256) {
        int r = 64 + (tid >> 1), i = tid & 1;
        int c = r / 64 - 1, p = r % 64;
        float acc = accb[r * 2 + i];
        float s = ss[p * 2 + i];
        float ds = sg[p * 2 + i] * acc;
        Jsh[p * 4 + i * 2 + c] = fmaf(ds, v2[p * 2 + i], (1.f + s) * v2[r * 2 + i]);
    }
    __syncthreads();
    if (tid < 64) {
        int p = tid, gp = gbase + p;
        float a = Jsh[p * 4 + 0], b_ = Jsh[p * 4 + 1];
        float c = Jsh[p * 4 + 2], d = Jsh[p * 4 + 3];
        float det = a * d - b_ * c;
        float n2 = a * a + b_ * b_ + c * c + d * d;
        float ia, ib, ic, id;
        if (fabsf(det) > 1e-10f * n2) {
            float inv = 1.f / det;
            ia = d * inv; ib = -b_ * inv; ic = -c * inv; id = a * inv;
        } else {
            float inv = (n2 > 0.f) ? 1.f / n2 : 0.f;
            ia = a * inv; ib = c * inv; ic = b_ * inv; id = d * inv;
        }
        float4 o; o.x = ia; o.y = ib; o.z = ic; o.w = id;
        *reinterpret_cast<float4*>(g_jinv + gp * 4) = o;
    }
}

// ====================== K2: vv net + yd + J^-1 * yd_n ======================
__global__ __launch_bounds__(320, 1) void k_vv(
    const float* __restrict__ w1, const float* __restrict__ b1, const float* __restrict__ a1p,
    const float* __restrict__ w2, const float* __restrict__ b2, const float* __restrict__ a2p,
    const float* __restrict__ w3, const float* __restrict__ b3) {
    extern __shared__ float sm[];
    float* ws   = sm;                  // 100*304 = 30400
    float* bufA = ws + 30400;          // 64*308 = 19712
    float* ys   = bufA + 19712;        // 128
    float* b2p  = ys + 128;            // 304   (cum 50544, even)
    ull* w3u    = (ull*)(b2p + 304);   // 304 ull = 608 floats
    float* dsum = b2p + 304 + 608;     // 128

    const int tid = threadIdx.x;
    const bool active = tid < 304;
    const int rg = tid / 38;
    const int og = tid % 38;
    const int row0 = rg * 8;
    const int jb = og * 8;
    const int gbase = blockIdx.x * 64;

    if (tid < 128) ys[tid] = g_y[blockIdx.x * 128 + tid];
    for (int i = tid; i < 304; i += 320) {
        b2p[i] = (i < 300) ? b2[i] : 0.f;
        w3u[i] = (i < 300) ? ((const ull*)w3)[i] : 0ULL;
    }
    if (tid < 128) dsum[tid] = b3[tid & 1];
    const float al1 = a1p[0], al2 = a2p[0];
    __syncthreads();

    // L1: 2 -> 300, PReLU
    for (int i = tid; i < 19200; i += 320) {
        int p = i / 300, j = i % 300;
        float v = fmaf(ys[p * 2], w1[j], fmaf(ys[p * 2 + 1], w1[300 + j], b1[j]));
        bufA[p * 308 + j] = (v >= 0.f) ? v : al1 * v;
    }
    __syncthreads();

    // L2: 300x300 GEMM, 3 K-chunks of 100
    ull acc[8][4];
#pragma unroll
    for (int r = 0; r < 8; r++)
#pragma unroll
        for (int q = 0; q < 4; q++) acc[r][q] = 0ULL;

    for (int c = 0; c < 3; c++) {
        for (int i = tid; i < 30400; i += 320) {
            int kk = i / 304, j = i % 304;
            ws[i] = (j < 300) ? w2[(c * 100 + kk) * 300 + j] : 0.f;
        }
        __syncthreads();
        if (active) {
            const int kb = c * 100;
            for (int k = 0; k < 100; k += 4) {
                ulonglong2 wA0 = *(const ulonglong2*)(ws + (k + 0) * 304 + jb);
                ulonglong2 wA1 = *(const ulonglong2*)(ws + (k + 0) * 304 + jb + 4);
                ulonglong2 wB0 = *(const ulonglong2*)(ws + (k + 1) * 304 + jb);
                ulonglong2 wB1 = *(const ulonglong2*)(ws + (k + 1) * 304 + jb + 4);
                ulonglong2 wC0 = *(const ulonglong2*)(ws + (k + 2) * 304 + jb);
                ulonglong2 wC1 = *(const ulonglong2*)(ws + (k + 2) * 304 + jb + 4);
                ulonglong2 wD0 = *(const ulonglong2*)(ws + (k + 3) * 304 + jb);
                ulonglong2 wD1 = *(const ulonglong2*)(ws + (k + 3) * 304 + jb + 4);
#pragma unroll
                for (int r = 0; r < 8; r++) {
                    float4 a = *(const float4*)(bufA + (row0 + r) * 308 + kb + k);
                    GS2(r, bc2(a.x), wA0, wA1)
                    GS2(r, bc2(a.y), wB0, wB1)
                    GS2(r, bc2(a.z), wC0, wC1)
                    GS2(r, bc2(a.w), wD0, wD1)
                }
            }
        }
        __syncthreads();
    }

    // PReLU + fused L3 partial dots (packed: lanes carry (d0,d1))
    if (active) {
#pragma unroll
        for (int r = 0; r < 8; r++) {
            ull d01 = 0ULL;
#pragma unroll
            for (int q = 0; q < 4; q++) {
                float h0, h1; upk2(acc[r][q], h0, h1);
                int j = jb + 2 * q;
                h0 += b2p[j]; h1 += b2p[j + 1];
                h0 = (h0 >= 0.f) ? h0 : al2 * h0;
                h1 = (h1 >= 0.f) ? h1 : al2 * h1;
                fma2(d01, bc2(h0), w3u[j]);
                fma2(d01, bc2(h1), w3u[j + 1]);
            }
            float d0, d1; upk2(d01, d0, d1);
            atomicAdd(&dsum[(row0 + r) * 2 + 0], d0);
            atomicAdd(&dsum[(row0 + r) * 2 + 1], d1);
        }
    }
    __syncthreads();

    if (tid < 64) {
        int p = tid, gp = gbase + p;
        float d0 = dsum[p * 2 + 0], d1 = dsum[p * 2 + 1];
        float y0 = ys[p * 2 + 0], y1 = ys[p * 2 + 1];
        float lsv = d0 * y0 + d1 * y1;
        float Vy = y0 * y0 + y1 * y1;
        float rl = fmaxf(fmaf(1e-4f, Vy, lsv), 0.f);
        float sc = rl / (Vy + 1e-12f);
        float yd0 = d0 - sc * y0, yd1 = d1 - sc * y1;
        float nrm = sqrtf(yd0 * yd0 + yd1 * yd1);
        float innv = 1.f / fmaxf(nrm, 1e-12f);
        float n0 = yd0 * innv, n1 = yd1 * innv;
        float4 Ji = *reinterpret_cast<const float4*>(g_jinv + gp * 4);
        g_xdh[gp * 2 + 0] = Ji.x * n0 + Ji.y * n1;
        g_xdh[gp * 2 + 1] = Ji.z * n0 + Ji.w * n1;
    }
}

// =================== K3: vel-scalar net + final scaling ====================
__global__ __launch_bounds__(224, 2) void k_vs(
    const float* __restrict__ x,
    const float* __restrict__ w1, const float* __restrict__ b1,
    const float* __restrict__ w2, const float* __restrict__ b2,
    const float* __restrict__ w3, const float* __restrict__ b3,
    float* __restrict__ out) {
    extern __shared__ float sm[];
    float* ws   = sm;                  // 100*104 = 10400
    float* bufA = ws + 10400;          // 128*108 = 13824
    float* xs   = bufA + 13824;        // 256
    float* b2p  = xs + 256;            // 104  (cum 24584, even)
    ull* w3u    = (ull*)(b2p + 104);   // 52 ull = 104 floats (pairs of w3)
    float* dsum = b2p + 104 + 104;     // 128

    const int tid = threadIdx.x;
    const bool active = tid < 208;
    const int rg = tid / 13;
    const int og = tid % 13;
    const int row0 = rg * 8;
    const int jb = og * 8;
    const int gbase = blockIdx.x * 128;

    for (int i = tid; i < 256; i += 224) xs[i] = x[blockIdx.x * 256 + i];
    for (int i = tid; i < 10400; i += 224) {
        int k = i / 104, j = i % 104;
        ws[i] = (j < 100) ? w2[k * 100 + j] : 0.f;
    }
    if (tid < 104) b2p[tid] = (tid < 100) ? b2[tid] : 0.f;
    if (tid < 52) w3u[tid] = (tid < 50) ? ((const ull*)w3)[tid] : 0ULL;
    if (tid < 128) dsum[tid] = b3[0];
    __syncthreads();

    // L1: 2 -> 100, leaky
    for (int i = tid; i < 12800; i += 224) {
        int p = i / 100, j = i % 100;
        float v = fmaf(xs[p * 2], w1[j], fmaf(xs[p * 2 + 1], w1[100 + j], b1[j]));
        bufA[p * 108 + j] = (v >= 0.f) ? v : 0.01f * v;
    }
    __syncthreads();

    // L2: 100x100 GEMM
    ull acc[8][4];
#pragma unroll
    for (int r = 0; r < 8; r++)
#pragma unroll
        for (int q = 0; q < 4; q++) acc[r][q] = 0ULL;
    if (active) {
        for (int k = 0; k < 100; k += 4) {
            ulonglong2 wA0 = *(const ulonglong2*)(ws + (k + 0) * 104 + jb);
            ulonglong2 wA1 = *(const ulonglong2*)(ws + (k + 0) * 104 + jb + 4);
            ulonglong2 wB0 = *(const ulonglong2*)(ws + (k + 1) * 104 + jb);
            ulonglong2 wB1 = *(const ulonglong2*)(ws + (k + 1) * 104 + jb + 4);
            ulonglong2 wC0 = *(const ulonglong2*)(ws + (k + 2) * 104 + jb);
            ulonglong2 wC1 = *(const ulonglong2*)(ws + (k + 2) * 104 + jb + 4);
            ulonglong2 wD0 = *(const ulonglong2*)(ws + (k + 3) * 104 + jb);
            ulonglong2 wD1 = *(const ulonglong2*)(ws + (k + 3) * 104 + jb + 4);
#pragma unroll
            for (int r = 0; r < 8; r++) {
                float4 a = *(const float4*)(bufA + (row0 + r) * 108 + k);
                GS2(r, bc2(a.x), wA0, wA1)
                GS2(r, bc2(a.y), wB0, wB1)
                GS2(r, bc2(a.z), wC0, wC1)
                GS2(r, bc2(a.w), wD0, wD1)
            }
        }
        // leaky + fused L3 partial dot (lanes then horizontal add)
#pragma unroll
        for (int r = 0; r < 8; r++) {
            ull dp2 = 0ULL;
#pragma unroll
            for (int q = 0; q < 4; q++) {
                float h0, h1; upk2(acc[r][q], h0, h1);
                int j = jb + 2 * q;
                h0 += b2p[j]; h1 += b2p[j + 1];
                h0 = (h0 >= 0.f) ? h0 : 0.01f * h0;
                h1 = (h1 >= 0.f) ? h1 : 0.01f * h1;
                fma2(dp2, pk2(h0, h1), w3u[j >> 1]);
            }
            float s0, s1; upk2(dp2, s0, s1);
            atomicAdd(&dsum[row0 + r], s0 + s1);
        }
    }
    __syncthreads();

    if (tid < 128) {
        int p = tid, gp = gbase + p;
        float t = dsum[p];
        float x0 = xs[p * 2 + 0], x1 = xs[p * 2 + 1];
        out[gp * 2 + 0] = (expf(t + x0) + 1e-12f) * g_xdh[gp * 2 + 0];
        out[gp * 2 + 1] = (expf(t + x1) + 1e-12f) * g_xdh[gp * 2 + 1];
    }
}

// ============================== launch =====================================
extern "C" void kernel_launch(void* const* d_in, const int* in_sizes, int n_in,
                              void* d_out, int out_size) {
    const float* x     = (const float*)d_in[0];
    const float* t1w1  = (const float*)d_in[1];
    const float* t1b1  = (const float*)d_in[2];
    const float* t1w2  = (const float*)d_in[3];
    const float* t1b2  = (const float*)d_in[4];
    const float* t1w3  = (const float*)d_in[5];
    const float* t1b3  = (const float*)d_in[6];
    const float* t2w1  = (const float*)d_in[7];
    const float* t2b1  = (const float*)d_in[8];
    const float* t2w2  = (const float*)d_in[9];
    const float* t2b2  = (const float*)d_in[10];
    const float* t2w3  = (const float*)d_in[11];
    const float* t2b3  = (const float*)d_in[12];
    const float* vvw1  = (const float*)d_in[13];
    const float* vvb1  = (const float*)d_in[14];
    const float* vva1  = (const float*)d_in[15];
    const float* vvw2  = (const float*)d_in[16];
    const float* vvb2  = (const float*)d_in[17];
    const float* vva2  = (const float*)d_in[18];
    const float* vvw3  = (const float*)d_in[19];
    const float* vvb3  = (const float*)d_in[20];
    const float* vsw1  = (const float*)d_in[21];
    const float* vsb1  = (const float*)d_in[22];
    const float* vsw2  = (const float*)d_in[23];
    const float* vsb2  = (const float*)d_in[24];
    const float* vsw3  = (const float*)d_in[25];
    const float* vsb3  = (const float*)d_in[26];

    const int SM1 = (10400 + 2 * 20736 + 128 + 384 + 128 + 128 + 256 + 384 + 104 + 400) * 4;  // 215,136
    const int SM2 = (30400 + 19712 + 128 + 304 + 608 + 128) * 4;                              // 205,120
    const int SM3 = (10400 + 13824 + 256 + 104 + 104 + 128) * 4;                              //  99,264

    cudaFuncSetAttribute(k_taskmap, cudaFuncAttributeMaxDynamicSharedMemorySize, SM1);
    cudaFuncSetAttribute(k_vv, cudaFuncAttributeMaxDynamicSharedMemorySize, SM2);
    cudaFuncSetAttribute(k_vs, cudaFuncAttributeMaxDynamicSharedMemorySize, SM3);

    k_origin<<<1, 128>>>(t1w1, t1b1, t1w2, t1b2, t1w3, t1b3,
                         t2w1, t2b1, t2w2, t2b2, t2w3, t2b3);
    k_taskmap<<<NPTS / 64, 320, SM1>>>(x, t1w1, t1b1, t1w2, t1b2, t1w3, t1b3,
                                       t2w1, t2b1, t2w2, t2b2, t2w3, t2b3);
    k_vv<<<NPTS / 64, 320, SM2>>>(vvw1, vvb1, vva1, vvw2, vvb2, vva2, vvw3, vvb3);
    k_vs<<<NPTS / 128, 224, SM3>>>(x, vsw1, vsb1, vsw2, vsb2, vsw3, vsb3,
                                   (float*)d_out);
}